// round 1
// baseline (speedup 1.0000x reference)
#include <cuda_runtime.h>
#include <math.h>
#include <stdint.h>

#define D 512
#define C 17
#define RMAX 131072
#define HSIZE 65536
#define CH 128
#define EQCAP 8192

// ---------------- device scratch (static; no allocation) ----------------
__device__ float        g_entnew[8192];
__device__ int          g_yhat[8192];
__device__ unsigned     g_entbits[RMAX];
__device__ int          g_cls[RMAX];
__device__ unsigned char g_selbyte[RMAX];
__device__ unsigned     g_hist[C * HSIZE];       // 4.45 MB
__device__ unsigned     g_prefix16[C];
__device__ int          g_kleft[C];
__device__ unsigned     g_thr[C];
__device__ int          g_needeq[C];
__device__ int          g_eqcnt[C];
__device__ int          g_eqlist[C][EQCAP];
__device__ float        g_part[(size_t)C * CH * D];  // 4.45 MB
__device__ float        g_Wcn[C * D];

// ---------------- kernel 1: logits -> entropy, argmax; also zero hist ----
__global__ void k_logits(const float* __restrict__ feat,
                         const float* __restrict__ w,
                         const float* __restrict__ bias, int B) {
    int tid = blockIdx.x * blockDim.x + threadIdx.x;
    int nth = gridDim.x * blockDim.x;
    for (int i = tid; i < C * HSIZE; i += nth) g_hist[i] = 0u;

    int warp = tid >> 5;
    int lane = threadIdx.x & 31;
    if (warp >= B) return;

    const float* f = feat + (size_t)warp * D;
    float fv[16];
#pragma unroll
    for (int j = 0; j < 16; j++) fv[j] = f[lane + 32 * j];

    float pc = -INFINITY;
#pragma unroll 1
    for (int c = 0; c < C; c++) {
        const float* wc = w + (size_t)c * D;
        float s = 0.f;
#pragma unroll
        for (int j = 0; j < 16; j++) s += fv[j] * wc[lane + 32 * j];
#pragma unroll
        for (int o = 16; o; o >>= 1) s += __shfl_xor_sync(0xffffffffu, s, o);
        if (lane == c) pc = s + bias[c];
    }
    // warp-wide max (lanes >= C hold -inf)
    float m = pc;
#pragma unroll
    for (int o = 16; o; o >>= 1) m = fmaxf(m, __shfl_xor_sync(0xffffffffu, m, o));

    float ex = (lane < C) ? expf(pc - m) : 0.f;
    float tt = (lane < C) ? ex * (pc - m) : 0.f;
    float S = ex, T = tt;
#pragma unroll
    for (int o = 16; o; o >>= 1) {
        S += __shfl_xor_sync(0xffffffffu, S, o);
        T += __shfl_xor_sync(0xffffffffu, T, o);
    }
    float ent = logf(S) - T / S;
    unsigned bal = __ballot_sync(0xffffffffu, (lane < C) && (pc == m));
    int amax = __ffs(bal) - 1;
    if (lane == 0) {
        g_entnew[warp] = ent;
        g_yhat[warp] = amax;
    }
}

// ---------------- kernel 2: build keys/class arrays + hist pass A --------
__global__ void k_prep(const float* __restrict__ entbank,
                       const int* __restrict__ labels, int N, int R) {
    int tid = blockIdx.x * blockDim.x + threadIdx.x;
    int nth = gridDim.x * blockDim.x;
    for (int i = tid; i < R; i += nth) {
        float e; int c;
        if (i < N) { e = entbank[i]; c = labels[i]; }
        else       { e = g_entnew[i - N]; c = g_yhat[i - N]; }
        unsigned bits = __float_as_uint(e);   // entropies >= 0: monotone
        g_entbits[i] = bits;
        g_cls[i] = c;
        g_selbyte[i] = 0;
        atomicAdd(&g_hist[c * HSIZE + (bits >> 16)], 1u);
    }
}

// ---------------- kernel 3: scan pass A (find top-16-bit prefix) ---------
__global__ void k_scanA(const int* __restrict__ kptr) {
    int c = blockIdx.x;
    int t = threadIdx.x;  // 1024 threads
    __shared__ unsigned part[1024];
    __shared__ int sh_k, sh_t, sh_base;
    unsigned* h = &g_hist[c * HSIZE + t * 64];
    unsigned s = 0;
#pragma unroll
    for (int q = 0; q < 64; q++) s += h[q];
    part[t] = s;
    __syncthreads();
    if (t == 0) {
        long long tot = 0;
        for (int j = 0; j < 1024; j++) tot += part[j];
        int Kf = kptr[0];
        long long kk = (tot < (long long)Kf) ? tot : (long long)Kf;
        int k = (int)kk;
        long long run = 0; int sel = 0;
        for (int j = 0; j < 1024; j++) {
            if (run + (long long)part[j] >= k) { sel = j; break; }
            run += part[j];
        }
        sh_k = k; sh_t = sel; sh_base = (int)run;
    }
    __syncthreads();
    if (t == sh_t) {
        int run = sh_base; int k = sh_k;
        unsigned pr = 0;
        for (int q = 0; q < 64; q++) {
            if (run + (int)h[q] >= k) { pr = (unsigned)(t * 64 + q); break; }
            run += (int)h[q];
        }
        g_prefix16[c] = pr;
        g_kleft[c] = k - run;
    }
    __syncthreads();
#pragma unroll
    for (int q = 0; q < 64; q++) h[q] = 0u;  // zero for pass B
}

// ---------------- kernel 4: hist pass B (low 16 bits, prefix-matched) ----
__global__ void k_histB(int R) {
    int tid = blockIdx.x * blockDim.x + threadIdx.x;
    int nth = gridDim.x * blockDim.x;
    for (int i = tid; i < R; i += nth) {
        unsigned bits = g_entbits[i];
        int c = g_cls[i];
        if ((bits >> 16) == g_prefix16[c])
            atomicAdd(&g_hist[c * HSIZE + (bits & 0xFFFFu)], 1u);
    }
}

// ---------------- kernel 5: scan pass B -> exact threshold + need_eq -----
__global__ void k_scanB() {
    int c = blockIdx.x;
    int t = threadIdx.x;
    __shared__ unsigned part[1024];
    __shared__ int sh_k, sh_t, sh_base;
    unsigned* h = &g_hist[c * HSIZE + t * 64];
    unsigned s = 0;
#pragma unroll
    for (int q = 0; q < 64; q++) s += h[q];
    part[t] = s;
    __syncthreads();
    if (t == 0) {
        int k = g_kleft[c];
        long long run = 0; int sel = 0;
        for (int j = 0; j < 1024; j++) {
            if (run + (long long)part[j] >= k) { sel = j; break; }
            run += part[j];
        }
        sh_k = k; sh_t = sel; sh_base = (int)run;
    }
    __syncthreads();
    if (t == sh_t) {
        int run = sh_base; int k = sh_k;
        unsigned low = 0;
        for (int q = 0; q < 64; q++) {
            if (run + (int)h[q] >= k) { low = (unsigned)(t * 64 + q); break; }
            run += (int)h[q];
        }
        g_thr[c] = (g_prefix16[c] << 16) | low;
        g_needeq[c] = k - run;   // #elements equal to thr to take (index order)
        g_eqcnt[c] = 0;
    }
}

// ---------------- kernel 6: gather rows equal to threshold ---------------
__global__ void k_eqgather(int R) {
    int tid = blockIdx.x * blockDim.x + threadIdx.x;
    int nth = gridDim.x * blockDim.x;
    for (int i = tid; i < R; i += nth) {
        int c = g_cls[i];
        if (g_entbits[i] == g_thr[c]) {
            int p = atomicAdd(&g_eqcnt[c], 1);
            if (p < EQCAP) g_eqlist[c][p] = i;
        }
    }
}

// ---------------- kernel 7: mark first need_eq equal rows by index -------
__global__ void k_eqmark() {
    int c = blockIdx.x;
    int need = g_needeq[c];
    if (need <= 0) return;
    int m = g_eqcnt[c]; if (m > EQCAP) m = EQCAP;
    __shared__ int lst[EQCAP];
    for (int j = threadIdx.x; j < m; j += blockDim.x) lst[j] = g_eqlist[c][j];
    __syncthreads();
    if (need >= m) {
        for (int j = threadIdx.x; j < m; j += blockDim.x) g_selbyte[lst[j]] = 1;
        return;
    }
    // rank = count of smaller indices; indices unique -> exact selection
    for (int j = threadIdx.x; j < m; j += blockDim.x) {
        int v = lst[j];
        int rank = 0;
        for (int q = 0; q < m; q++) rank += (lst[q] < v);
        if (rank < need) g_selbyte[v] = 1;
    }
}

// ---------------- kernel 8: normalized per-class support sums ------------
__global__ void k_sum(const float* __restrict__ supports,
                      const float* __restrict__ feat, int N, int R) {
    int c = blockIdx.y;
    int chunk = blockIdx.x;
    int per = (R + CH - 1) / CH;
    int s0 = chunk * per;
    int s1 = s0 + per; if (s1 > R) s1 = R;

    __shared__ float acc[D];
    for (int d = threadIdx.x; d < D; d += blockDim.x) acc[d] = 0.f;
    __syncthreads();

    unsigned thr = g_thr[c];
    int w = threadIdx.x >> 5, lane = threadIdx.x & 31;

    for (int base = s0 + w * 32; base < s1; base += 8 * 32) {
        int i = base + lane;
        bool sel = false;
        if (i < s1 && g_cls[i] == c) {
            unsigned bits = g_entbits[i];
            sel = (bits < thr) || (bits == thr && g_selbyte[i]);
        }
        unsigned mask = __ballot_sync(0xffffffffu, sel);
        while (mask) {
            int bpos = __ffs(mask) - 1;
            mask &= mask - 1;
            int r = base + bpos;
            const float* p = (r < N) ? supports + (size_t)r * D
                                     : feat + (size_t)(r - N) * D;
            float v[16]; float ss = 0.f;
#pragma unroll
            for (int j = 0; j < 16; j++) {
                v[j] = p[lane + 32 * j];
                ss += v[j] * v[j];
            }
#pragma unroll
            for (int o = 16; o; o >>= 1) ss += __shfl_xor_sync(0xffffffffu, ss, o);
            float rn = 1.f / fmaxf(sqrtf(ss), 1e-12f);
#pragma unroll
            for (int j = 0; j < 16; j++)
                atomicAdd(&acc[lane + 32 * j], v[j] * rn);
        }
    }
    __syncthreads();
    float* dst = &g_part[((size_t)c * CH + chunk) * D];
    for (int d = threadIdx.x; d < D; d += blockDim.x) dst[d] = acc[d];
}

// ---------------- kernel 9: reduce partials + column-normalize -----------
__global__ void k_finalW() {
    int c = blockIdx.x;
    int t = threadIdx.x;  // 256
    float s0 = 0.f, s1 = 0.f;
    for (int j = 0; j < CH; j++) {
        const float* p = &g_part[((size_t)c * CH + j) * D];
        s0 += p[t];
        s1 += p[t + 256];
    }
    // block reduce sum of squares
    float ss = s0 * s0 + s1 * s1;
    __shared__ float red[8];
#pragma unroll
    for (int o = 16; o; o >>= 1) ss += __shfl_xor_sync(0xffffffffu, ss, o);
    if ((t & 31) == 0) red[t >> 5] = ss;
    __syncthreads();
    float tot;
    {
        float v = (t < 8) ? red[t] : 0.f;
#pragma unroll
        for (int o = 4; o; o >>= 1) v += __shfl_xor_sync(0xffffffffu, v, o);
        __shared__ float sh_tot;
        if (t == 0) sh_tot = v;
        __syncthreads();
        tot = sh_tot;
    }
    float rn = 1.f / fmaxf(sqrtf(tot), 1e-12f);
    g_Wcn[c * D + t] = s0 * rn;
    g_Wcn[c * D + t + 256] = s1 * rn;
}

// ---------------- kernel 10: final GEMM out = feature @ w_norm -----------
__global__ void k_gemm2(const float* __restrict__ feat, float* __restrict__ out,
                        int B) {
    int tid = blockIdx.x * blockDim.x + threadIdx.x;
    int warp = tid >> 5;
    int lane = threadIdx.x & 31;
    if (warp >= B) return;
    const float* f = feat + (size_t)warp * D;
    float fv[16];
#pragma unroll
    for (int j = 0; j < 16; j++) fv[j] = f[lane + 32 * j];
    float myv = 0.f;
#pragma unroll 1
    for (int c = 0; c < C; c++) {
        const float* wc = &g_Wcn[c * D];
        float s = 0.f;
#pragma unroll
        for (int j = 0; j < 16; j++) s += fv[j] * wc[lane + 32 * j];
#pragma unroll
        for (int o = 16; o; o >>= 1) s += __shfl_xor_sync(0xffffffffu, s, o);
        if (lane == c) myv = s;
    }
    if (lane < C) out[(size_t)warp * C + lane] = myv;
}

// ---------------- launch ---------------------------------------------------
extern "C" void kernel_launch(void* const* d_in, const int* in_sizes, int n_in,
                              void* d_out, int out_size) {
    const float* feature  = (const float*)d_in[0];
    const float* clf_w    = (const float*)d_in[1];
    const float* clf_b    = (const float*)d_in[2];
    const float* supports = (const float*)d_in[3];
    const float* ent_bank = (const float*)d_in[4];
    const int*   labels   = (const int*)d_in[5];   // low 32 bits are the label either way
    const int*   kptr     = (const int*)d_in[6];

    int Cc = in_sizes[2];          // 17
    int Dv = in_sizes[1] / Cc;     // 512
    int B  = in_sizes[0] / Dv;     // 4096
    int N  = in_sizes[4];          // 100000
    int R  = N + B;
    (void)n_in; (void)out_size; (void)Dv;

    float* out = (float*)d_out;

    int blk1 = (B * 32 + 255) / 256;
    k_logits<<<blk1, 256>>>(feature, clf_w, clf_b, B);
    k_prep<<<256, 256>>>(ent_bank, labels, N, R);
    k_scanA<<<C, 1024>>>(kptr);
    k_histB<<<256, 256>>>(R);
    k_scanB<<<C, 1024>>>();
    k_eqgather<<<128, 256>>>(R);
    k_eqmark<<<C, 256>>>();
    dim3 g8(CH, C);
    k_sum<<<g8, 256>>>(supports, feature, N, R);
    k_finalW<<<C, 256>>>();
    k_gemm2<<<blk1, 256>>>(feature, out, B);
}

// round 2
// speedup vs baseline: 2.2838x; 2.2838x over previous
#include <cuda_runtime.h>
#include <math.h>
#include <stdint.h>

#define D 512
#define C 17
#define RMAX 131072
#define NBA 4096
#define NBB 4096
#define NBC 256
#define EQCAP 4096
#define LCAP 32768
#define CH2 16

// ---------------- device scratch (static; no allocation) ----------------
__device__ float         g_entnew[8192];
__device__ int           g_yhat[8192];
__device__ unsigned      g_entbits[RMAX];
__device__ int           g_cls[RMAX];
__device__ unsigned      g_histA[C * NBA];
__device__ unsigned      g_histB[C * NBB];
__device__ unsigned      g_histC[C * NBC];
__device__ unsigned      g_prefA[C];    // 12-bit
__device__ unsigned      g_prefAB[C];   // 24-bit
__device__ unsigned      g_thr[C];      // 32-bit exact threshold
__device__ int           g_kleft[C];
__device__ int           g_needeq[C];
__device__ int           g_cnt[C];
__device__ int           g_eqcnt[C];
__device__ int           g_eqlist[C][EQCAP];
__device__ int           g_list[(size_t)C * LCAP];
__device__ float         g_part[(size_t)C * CH2 * D];
__device__ float         g_Wcn[C * D];

// ---------------- kernel 1: logits -> entropy, argmax; zero scratch ------
__global__ void k_logits(const float* __restrict__ feat,
                         const float* __restrict__ w,
                         const float* __restrict__ bias, int B) {
    int tid = blockIdx.x * blockDim.x + threadIdx.x;
    int nth = gridDim.x * blockDim.x;
    for (int i = tid; i < C * NBA; i += nth) g_histA[i] = 0u;
    for (int i = tid; i < C * NBB; i += nth) g_histB[i] = 0u;
    for (int i = tid; i < C * NBC; i += nth) g_histC[i] = 0u;
    if (tid < C) { g_cnt[tid] = 0; g_eqcnt[tid] = 0; }

    int warp = tid >> 5;
    int lane = threadIdx.x & 31;
    if (warp >= B) return;

    const float* f = feat + (size_t)warp * D;
    float fv[16];
#pragma unroll
    for (int j = 0; j < 16; j++) fv[j] = f[lane + 32 * j];

    float pc = -INFINITY;
#pragma unroll 1
    for (int c = 0; c < C; c++) {
        const float* wc = w + (size_t)c * D;
        float s = 0.f;
#pragma unroll
        for (int j = 0; j < 16; j++) s += fv[j] * wc[lane + 32 * j];
#pragma unroll
        for (int o = 16; o; o >>= 1) s += __shfl_xor_sync(0xffffffffu, s, o);
        if (lane == c) pc = s + bias[c];
    }
    float m = pc;
#pragma unroll
    for (int o = 16; o; o >>= 1) m = fmaxf(m, __shfl_xor_sync(0xffffffffu, m, o));

    float ex = (lane < C) ? expf(pc - m) : 0.f;
    float tt = (lane < C) ? ex * (pc - m) : 0.f;
    float S = ex, T = tt;
#pragma unroll
    for (int o = 16; o; o >>= 1) {
        S += __shfl_xor_sync(0xffffffffu, S, o);
        T += __shfl_xor_sync(0xffffffffu, T, o);
    }
    float ent = logf(S) - T / S;
    unsigned bal = __ballot_sync(0xffffffffu, (lane < C) && (pc == m));
    int amax = __ffs(bal) - 1;
    if (lane == 0) {
        g_entnew[warp] = ent;
        g_yhat[warp] = amax;
    }
}

// ---------------- kernel 2: build keys/class arrays + hist pass A --------
__global__ void k_prep(const float* __restrict__ entbank,
                       const int* __restrict__ labels, int N, int R) {
    int tid = blockIdx.x * blockDim.x + threadIdx.x;
    int nth = gridDim.x * blockDim.x;
    for (int i = tid; i < R; i += nth) {
        float e; int c;
        if (i < N) { e = entbank[i]; c = labels[i]; }
        else       { e = g_entnew[i - N]; c = g_yhat[i - N]; }
        unsigned bits = __float_as_uint(e);   // entropies >= 0: monotone
        g_entbits[i] = bits;
        g_cls[i] = c;
        atomicAdd(&g_histA[c * NBA + (bits >> 20)], 1u);
    }
}

// ---------------- generic block scan: find bin containing k-th -----------
__device__ __forceinline__ void scan_block(const unsigned* __restrict__ h,
                                           int nb, int k,
                                           unsigned& bin, int& kleft) {
    __shared__ unsigned part[256];
    __shared__ int sh_t, sh_base;
    __shared__ unsigned sh_bin;
    __shared__ int sh_kl;
    int t = threadIdx.x;
    int q = nb >> 8;
    unsigned s = 0;
#pragma unroll 4
    for (int j = 0; j < q; j++) s += h[t * q + j];
    part[t] = s;
    __syncthreads();
    if (t == 0) {
        int run = 0, sel = 0;
        for (int j = 0; j < 256; j++) {
            if (run + (int)part[j] >= k) { sel = j; break; }
            run += (int)part[j];
        }
        sh_t = sel; sh_base = run;
        sh_bin = 0; sh_kl = 0;
    }
    __syncthreads();
    if (t == sh_t) {
        int run = sh_base;
        for (int j = 0; j < q; j++) {
            unsigned v = h[t * q + j];
            if (run + (int)v >= k) { sh_bin = (unsigned)(t * q + j); sh_kl = k - run; break; }
            run += (int)v;
        }
    }
    __syncthreads();
    bin = sh_bin; kleft = sh_kl;
}

// ---------------- kernel 3: scan pass A ----------------------------------
__global__ void k_scanA(const int* __restrict__ kptr) {
    int c = blockIdx.x;
    const unsigned* h = &g_histA[c * NBA];
    // total count for this class
    __shared__ int sh_tot;
    {
        int t = threadIdx.x;
        unsigned s = 0;
        for (int j = 0; j < NBA / 256; j++) s += h[t * (NBA / 256) + j];
        __shared__ unsigned red[256];
        red[t] = s;
        __syncthreads();
        if (t == 0) {
            long long tot = 0;
            for (int j = 0; j < 256; j++) tot += red[j];
            sh_tot = (int)tot;
        }
        __syncthreads();
    }
    int Kf = kptr[0];
    int k = sh_tot < Kf ? sh_tot : Kf;
    if (k <= 0) {
        if (threadIdx.x == 0) { g_prefA[c] = 0; g_kleft[c] = 0; }
        return;
    }
    unsigned bin; int kl;
    scan_block(h, NBA, k, bin, kl);
    if (threadIdx.x == 0) { g_prefA[c] = bin; g_kleft[c] = kl; }
}

// ---------------- kernel 4: hist pass B ----------------------------------
__global__ void k_histB(int R) {
    int tid = blockIdx.x * blockDim.x + threadIdx.x;
    int nth = gridDim.x * blockDim.x;
    for (int i = tid; i < R; i += nth) {
        unsigned bits = g_entbits[i];
        int c = g_cls[i];
        if ((bits >> 20) == g_prefA[c])
            atomicAdd(&g_histB[c * NBB + ((bits >> 8) & 0xFFFu)], 1u);
    }
}

// ---------------- kernel 5: scan pass B ----------------------------------
__global__ void k_scanB() {
    int c = blockIdx.x;
    int k = g_kleft[c];
    if (k <= 0) {
        if (threadIdx.x == 0) g_prefAB[c] = g_prefA[c] << 12;
        return;
    }
    unsigned bin; int kl;
    scan_block(&g_histB[c * NBB], NBB, k, bin, kl);
    if (threadIdx.x == 0) {
        g_prefAB[c] = (g_prefA[c] << 12) | bin;
        g_kleft[c] = kl;
    }
}

// ---------------- kernel 6: hist pass C ----------------------------------
__global__ void k_histC(int R) {
    int tid = blockIdx.x * blockDim.x + threadIdx.x;
    int nth = gridDim.x * blockDim.x;
    for (int i = tid; i < R; i += nth) {
        unsigned bits = g_entbits[i];
        int c = g_cls[i];
        if ((bits >> 8) == g_prefAB[c])
            atomicAdd(&g_histC[c * NBC + (bits & 0xFFu)], 1u);
    }
}

// ---------------- kernel 7: scan pass C -> exact threshold ---------------
__global__ void k_scanC() {
    int c = blockIdx.x;
    int k = g_kleft[c];
    if (k <= 0) {
        if (threadIdx.x == 0) { g_thr[c] = g_prefAB[c] << 8; g_needeq[c] = 0; }
        return;
    }
    unsigned bin; int kl;
    scan_block(&g_histC[c * NBC], NBC, k, bin, kl);
    if (threadIdx.x == 0) {
        g_thr[c] = (g_prefAB[c] << 8) | bin;
        g_needeq[c] = kl;   // # of rows equal to thr to take (index order)
    }
}

// ---------------- kernel 8: compact strict-below rows + gather equals ----
__global__ void k_compact(int R) {
    int tid = blockIdx.x * blockDim.x + threadIdx.x;
    int nth = gridDim.x * blockDim.x;
    for (int i = tid; i < R; i += nth) {
        int c = g_cls[i];
        unsigned bits = g_entbits[i];
        unsigned thr = g_thr[c];
        if (bits < thr) {
            int p = atomicAdd(&g_cnt[c], 1);
            if (p < LCAP) g_list[(size_t)c * LCAP + p] = i;
        } else if (bits == thr) {
            int p = atomicAdd(&g_eqcnt[c], 1);
            if (p < EQCAP) g_eqlist[c][p] = i;
        }
    }
}

// ---------------- kernel 9: append first need_eq equal rows (by index) ---
__global__ void k_eqmark() {
    int c = blockIdx.x;
    int need = g_needeq[c];
    if (need <= 0) return;
    int m = g_eqcnt[c]; if (m > EQCAP) m = EQCAP;
    __shared__ int lst[EQCAP];
    for (int j = threadIdx.x; j < m; j += blockDim.x) lst[j] = g_eqlist[c][j];
    __syncthreads();
    if (need >= m) {
        for (int j = threadIdx.x; j < m; j += blockDim.x) {
            int p = atomicAdd(&g_cnt[c], 1);
            if (p < LCAP) g_list[(size_t)c * LCAP + p] = lst[j];
        }
        return;
    }
    for (int j = threadIdx.x; j < m; j += blockDim.x) {
        int v = lst[j];
        int rank = 0;
        for (int q = 0; q < m; q++) rank += (lst[q] < v);
        if (rank < need) {
            int p = atomicAdd(&g_cnt[c], 1);
            if (p < LCAP) g_list[(size_t)c * LCAP + p] = v;
        }
    }
}

// ---------------- kernel 10: normalized per-class support sums -----------
// grid (CH2, C); 256 threads = 8 warps; register accumulation per warp.
__global__ void k_sum(const float* __restrict__ supports,
                      const float* __restrict__ feat, int N) {
    int c = blockIdx.y;
    int blk = blockIdx.x;
    int cnt = g_cnt[c]; if (cnt > LCAP) cnt = LCAP;
    int w = threadIdx.x >> 5, lane = threadIdx.x & 31;
    int wg = blk * 8 + w;                 // 0..127 within class
    const int* lst = &g_list[(size_t)c * LCAP];

    float acc[16];
#pragma unroll
    for (int j = 0; j < 16; j++) acc[j] = 0.f;

    for (int idx = wg; idx < cnt; idx += CH2 * 8) {
        int r = lst[idx];
        const float4* p = (const float4*)((r < N) ? supports + (size_t)r * D
                                                  : feat + (size_t)(r - N) * D);
        float4 v[4];
        float ss = 0.f;
#pragma unroll
        for (int j = 0; j < 4; j++) {
            v[j] = p[lane + 32 * j];
            ss += v[j].x * v[j].x + v[j].y * v[j].y + v[j].z * v[j].z + v[j].w * v[j].w;
        }
#pragma unroll
        for (int o = 16; o; o >>= 1) ss += __shfl_xor_sync(0xffffffffu, ss, o);
        float rn = 1.f / fmaxf(sqrtf(ss), 1e-12f);
#pragma unroll
        for (int j = 0; j < 4; j++) {
            acc[4 * j + 0] += v[j].x * rn;
            acc[4 * j + 1] += v[j].y * rn;
            acc[4 * j + 2] += v[j].z * rn;
            acc[4 * j + 3] += v[j].w * rn;
        }
    }

    __shared__ float sacc[D];
    for (int d = threadIdx.x; d < D; d += blockDim.x) sacc[d] = 0.f;
    __syncthreads();
#pragma unroll
    for (int j = 0; j < 4; j++) {
        int d = 4 * (lane + 32 * j);
        atomicAdd(&sacc[d + 0], acc[4 * j + 0]);
        atomicAdd(&sacc[d + 1], acc[4 * j + 1]);
        atomicAdd(&sacc[d + 2], acc[4 * j + 2]);
        atomicAdd(&sacc[d + 3], acc[4 * j + 3]);
    }
    __syncthreads();
    float* dst = &g_part[((size_t)c * CH2 + blk) * D];
    for (int d = threadIdx.x; d < D; d += blockDim.x) dst[d] = sacc[d];
}

// ---------------- kernel 11: reduce partials + column-normalize ----------
__global__ void k_finalW() {
    int c = blockIdx.x;
    int t = threadIdx.x;  // 256
    float s0 = 0.f, s1 = 0.f;
#pragma unroll
    for (int j = 0; j < CH2; j++) {
        const float* p = &g_part[((size_t)c * CH2 + j) * D];
        s0 += p[t];
        s1 += p[t + 256];
    }
    float ss = s0 * s0 + s1 * s1;
    __shared__ float red[8];
#pragma unroll
    for (int o = 16; o; o >>= 1) ss += __shfl_xor_sync(0xffffffffu, ss, o);
    if ((t & 31) == 0) red[t >> 5] = ss;
    __syncthreads();
    float tot;
    {
        float v = (t < 8) ? red[t] : 0.f;
#pragma unroll
        for (int o = 4; o; o >>= 1) v += __shfl_xor_sync(0xffffffffu, v, o);
        __shared__ float sh_tot;
        if (t == 0) sh_tot = v;
        __syncthreads();
        tot = sh_tot;
    }
    float rn = 1.f / fmaxf(sqrtf(tot), 1e-12f);
    g_Wcn[c * D + t] = s0 * rn;
    g_Wcn[c * D + t + 256] = s1 * rn;
}

// ---------------- kernel 12: final GEMM out = feature @ w_norm -----------
__global__ void k_gemm2(const float* __restrict__ feat, float* __restrict__ out,
                        int B) {
    int tid = blockIdx.x * blockDim.x + threadIdx.x;
    int warp = tid >> 5;
    int lane = threadIdx.x & 31;
    if (warp >= B) return;
    const float* f = feat + (size_t)warp * D;
    float fv[16];
#pragma unroll
    for (int j = 0; j < 16; j++) fv[j] = f[lane + 32 * j];
    float myv = 0.f;
#pragma unroll 1
    for (int c = 0; c < C; c++) {
        const float* wc = &g_Wcn[c * D];
        float s = 0.f;
#pragma unroll
        for (int j = 0; j < 16; j++) s += fv[j] * wc[lane + 32 * j];
#pragma unroll
        for (int o = 16; o; o >>= 1) s += __shfl_xor_sync(0xffffffffu, s, o);
        if (lane == c) myv = s;
    }
    if (lane < C) out[(size_t)warp * C + lane] = myv;
}

// ---------------- launch ---------------------------------------------------
extern "C" void kernel_launch(void* const* d_in, const int* in_sizes, int n_in,
                              void* d_out, int out_size) {
    const float* feature  = (const float*)d_in[0];
    const float* clf_w    = (const float*)d_in[1];
    const float* clf_b    = (const float*)d_in[2];
    const float* supports = (const float*)d_in[3];
    const float* ent_bank = (const float*)d_in[4];
    const int*   labels   = (const int*)d_in[5];
    const int*   kptr     = (const int*)d_in[6];

    int Cc = in_sizes[2];          // 17
    int Dv = in_sizes[1] / Cc;     // 512
    int B  = in_sizes[0] / Dv;     // 4096
    int N  = in_sizes[4];          // 100000
    int R  = N + B;
    (void)n_in; (void)out_size; (void)Dv;

    float* out = (float*)d_out;

    int blk1 = (B * 32 + 255) / 256;
    k_logits<<<blk1, 256>>>(feature, clf_w, clf_b, B);
    k_prep<<<256, 256>>>(ent_bank, labels, N, R);
    k_scanA<<<C, 256>>>(kptr);
    k_histB<<<256, 256>>>(R);
    k_scanB<<<C, 256>>>();
    k_histC<<<256, 256>>>(R);
    k_scanC<<<C, 256>>>();
    k_compact<<<256, 256>>>(R);
    k_eqmark<<<C, 256>>>();
    dim3 g10(CH2, C);
    k_sum<<<g10, 256>>>(supports, feature, N);
    k_finalW<<<C, 256>>>();
    k_gemm2<<<blk1, 256>>>(feature, out, B);
}

// round 3
// speedup vs baseline: 2.4318x; 1.0648x over previous
#include <cuda_runtime.h>
#include <math.h>
#include <stdint.h>

#define D 512
#define C 17
#define RMAX 131072
#define NBA 4096
#define CANDCAP 32768
#define LCAP 4096
#define CH2 32

// ---------------- device scratch (static; zero-init at module load) -------
__device__ unsigned g_entbits[RMAX];
__device__ int      g_cls[RMAX];
__device__ unsigned g_histA[C * NBA];   // re-zeroed by k_sel each run
__device__ unsigned g_prefA[C];
__device__ int      g_kleft[C];
__device__ int      g_cnt[C];
__device__ int      g_candcnt[C];
__device__ int      g_cand[C][CANDCAP];
__device__ int      g_list[(size_t)C * LCAP];
__device__ float    g_part[(size_t)C * CH2 * D];
__device__ float    g_Wcn[C * D];

// ---- kernel 1: bank keys + new-row logits/entropy/argmax, hist pass A ----
__global__ void k_logits(const float* __restrict__ feat,
                         const float* __restrict__ w,
                         const float* __restrict__ bias,
                         const float* __restrict__ entbank,
                         const int*   __restrict__ labels,
                         int B, int N) {
    int tid = blockIdx.x * blockDim.x + threadIdx.x;
    int nth = gridDim.x * blockDim.x;
    // bank rows: keys + histogram
    for (int i = tid; i < N; i += nth) {
        unsigned bits = __float_as_uint(entbank[i]);  // entropies >= 0: monotone
        int c = labels[i];
        g_entbits[i] = bits;
        g_cls[i] = c;
        atomicAdd(&g_histA[c * NBA + (bits >> 20)], 1u);
    }

    int warp = tid >> 5;
    int lane = threadIdx.x & 31;
    if (warp >= B) return;

    const float* f = feat + (size_t)warp * D;
    float fv[16];
#pragma unroll
    for (int j = 0; j < 16; j++) fv[j] = f[lane + 32 * j];

    float pc = -INFINITY;
#pragma unroll 1
    for (int c = 0; c < C; c++) {
        const float* wc = w + (size_t)c * D;
        float s = 0.f;
#pragma unroll
        for (int j = 0; j < 16; j++) s += fv[j] * wc[lane + 32 * j];
#pragma unroll
        for (int o = 16; o; o >>= 1) s += __shfl_xor_sync(0xffffffffu, s, o);
        if (lane == c) pc = s + bias[c];
    }
    float m = pc;
#pragma unroll
    for (int o = 16; o; o >>= 1) m = fmaxf(m, __shfl_xor_sync(0xffffffffu, m, o));

    float ex = (lane < C) ? expf(pc - m) : 0.f;
    float tt = (lane < C) ? ex * (pc - m) : 0.f;
    float S = ex, T = tt;
#pragma unroll
    for (int o = 16; o; o >>= 1) {
        S += __shfl_xor_sync(0xffffffffu, S, o);
        T += __shfl_xor_sync(0xffffffffu, T, o);
    }
    float ent = logf(S) - T / S;
    unsigned bal = __ballot_sync(0xffffffffu, (lane < C) && (pc == m));
    int amax = __ffs(bal) - 1;
    if (lane == 0) {
        unsigned bits = __float_as_uint(ent);
        g_entbits[N + warp] = bits;
        g_cls[N + warp] = amax;
        atomicAdd(&g_histA[amax * NBA + (bits >> 20)], 1u);
    }
}

// ---- kernel 2: scan pass A -> 12-bit bin per class; zero counters --------
__global__ void k_scanA(const int* __restrict__ kptr) {
    int c = blockIdx.x;
    int t = threadIdx.x;  // 256
    const unsigned* h = &g_histA[c * NBA];
    __shared__ unsigned part[256];
    __shared__ int sh_tot, sh_t, sh_base, sh_k;
    unsigned s = 0;
#pragma unroll
    for (int j = 0; j < 16; j++) s += h[t * 16 + j];
    part[t] = s;
    __syncthreads();
    if (t == 0) {
        g_cnt[c] = 0;
        g_candcnt[c] = 0;
        long long tot = 0;
        for (int j = 0; j < 256; j++) tot += part[j];
        int Kf = kptr[0];
        int k = (tot < (long long)Kf) ? (int)tot : Kf;
        sh_tot = k;
        if (k > 0) {
            int run = 0, sel = 0;
            for (int j = 0; j < 256; j++) {
                if (run + (int)part[j] >= k) { sel = j; break; }
                run += (int)part[j];
            }
            sh_t = sel; sh_base = run; sh_k = k;
        } else {
            g_prefA[c] = 0u;
            g_kleft[c] = 0;
        }
    }
    __syncthreads();
    if (sh_tot <= 0) return;
    if (t == sh_t) {
        int run = sh_base, k = sh_k;
        for (int q = 0; q < 16; q++) {
            unsigned v = h[t * 16 + q];
            if (run + (int)v >= k) {
                g_prefA[c] = (unsigned)(t * 16 + q);
                g_kleft[c] = k - run;
                break;
            }
            run += (int)v;
        }
    }
}

// ---- kernel 3: compact strict-below rows + gather pass-A-bin candidates --
__global__ void k_compact(int R) {
    __shared__ unsigned s_pref[C];
    if (threadIdx.x < C) s_pref[threadIdx.x] = g_prefA[threadIdx.x];
    __syncthreads();
    int tid = blockIdx.x * blockDim.x + threadIdx.x;
    int nth = gridDim.x * blockDim.x;
    for (int i = tid; i < R; i += nth) {
        int c = g_cls[i];
        unsigned b = g_entbits[i] >> 20;
        unsigned pa = s_pref[c];
        if (b < pa) {
            int p = atomicAdd(&g_cnt[c], 1);
            g_list[(size_t)c * LCAP + p] = i;
        } else if (b == pa) {
            int p = atomicAdd(&g_candcnt[c], 1);
            if (p < CANDCAP) g_cand[c][p] = i;
        }
    }
}

// ---- kernel 4: exact select among candidates (radix over low 20 bits) ----
__global__ void k_sel() {
    int c = blockIdx.x;
    int t = threadIdx.x;  // 256
    __shared__ unsigned hist[256];
    __shared__ int sh_bin, sh_kk;
    int k = g_kleft[c];
    int m = g_candcnt[c]; if (m > CANDCAP) m = CANDCAP;
    const int* lst = g_cand[c];

    if (k > 0 && m > 0) {
        unsigned prefix = 0;
        int kk = k;
        const int shifts[3] = {12, 4, 0};
        const int widths[3] = {8, 8, 4};
#pragma unroll 1
        for (int p = 0; p < 3; p++) {
            int sh = shifts[p], wb = widths[p];
            int bins = 1 << wb;
            if (t < 256) hist[t] = 0;
            __syncthreads();
            for (int j = t; j < m; j += 256) {
                unsigned low = g_entbits[lst[j]] & 0xFFFFFu;
                if ((low >> (sh + wb)) == prefix)
                    atomicAdd(&hist[(low >> sh) & (bins - 1)], 1u);
            }
            __syncthreads();
            if (t == 0) {
                int run = 0, bsel = 0;
                for (int b = 0; b < bins; b++) {
                    if (run + (int)hist[b] >= kk) { bsel = b; kk -= run; break; }
                    run += (int)hist[b];
                }
                sh_bin = bsel; sh_kk = kk;
            }
            __syncthreads();
            prefix = (prefix << wb) | (unsigned)sh_bin;
            kk = sh_kk;
            __syncthreads();
        }
        unsigned thrLow = prefix;
        int need = kk;
        for (int j = t; j < m; j += 256) {
            int idx = lst[j];
            unsigned low = g_entbits[idx] & 0xFFFFFu;
            if (low < thrLow) {
                int p2 = atomicAdd(&g_cnt[c], 1);
                g_list[(size_t)c * LCAP + p2] = idx;
            } else if (low == thrLow) {
                int rank = 0;
                for (int q = 0; q < m; q++) {
                    int iq = lst[q];
                    if (iq < idx && (g_entbits[iq] & 0xFFFFFu) == thrLow) rank++;
                }
                if (rank < need) {
                    int p2 = atomicAdd(&g_cnt[c], 1);
                    g_list[(size_t)c * LCAP + p2] = idx;
                }
            }
        }
    }
    // restore zero-histogram invariant for the next run
    for (int i = t; i < NBA; i += 256) g_histA[c * NBA + i] = 0u;
}

// ---- kernel 5: normalized per-class support sums (register accumulate) ---
__global__ void k_sum(const float* __restrict__ supports,
                      const float* __restrict__ feat, int N) {
    int c = blockIdx.y;
    int blk = blockIdx.x;
    int cnt = g_cnt[c]; if (cnt > LCAP) cnt = LCAP;
    int w = threadIdx.x >> 5, lane = threadIdx.x & 31;
    int wg = blk * 8 + w;
    const int* lst = &g_list[(size_t)c * LCAP];

    float acc[16];
#pragma unroll
    for (int j = 0; j < 16; j++) acc[j] = 0.f;

#pragma unroll 2
    for (int idx = wg; idx < cnt; idx += CH2 * 8) {
        int r = lst[idx];
        const float4* p = (const float4*)((r < N) ? supports + (size_t)r * D
                                                  : feat + (size_t)(r - N) * D);
        float4 v[4];
        float ss = 0.f;
#pragma unroll
        for (int j = 0; j < 4; j++) {
            v[j] = p[lane + 32 * j];
            ss += v[j].x * v[j].x + v[j].y * v[j].y + v[j].z * v[j].z + v[j].w * v[j].w;
        }
#pragma unroll
        for (int o = 16; o; o >>= 1) ss += __shfl_xor_sync(0xffffffffu, ss, o);
        float rn = 1.f / fmaxf(sqrtf(ss), 1e-12f);
#pragma unroll
        for (int j = 0; j < 4; j++) {
            acc[4 * j + 0] += v[j].x * rn;
            acc[4 * j + 1] += v[j].y * rn;
            acc[4 * j + 2] += v[j].z * rn;
            acc[4 * j + 3] += v[j].w * rn;
        }
    }

    __shared__ float sacc[D];
    for (int d = threadIdx.x; d < D; d += blockDim.x) sacc[d] = 0.f;
    __syncthreads();
#pragma unroll
    for (int j = 0; j < 4; j++) {
        int d = 4 * (lane + 32 * j);
        atomicAdd(&sacc[d + 0], acc[4 * j + 0]);
        atomicAdd(&sacc[d + 1], acc[4 * j + 1]);
        atomicAdd(&sacc[d + 2], acc[4 * j + 2]);
        atomicAdd(&sacc[d + 3], acc[4 * j + 3]);
    }
    __syncthreads();
    float* dst = &g_part[((size_t)c * CH2 + blk) * D];
    for (int d = threadIdx.x; d < D; d += blockDim.x) dst[d] = sacc[d];
}

// ---- kernel 6: reduce partials + column-normalize ------------------------
__global__ void k_finalW() {
    int c = blockIdx.x;
    int t = threadIdx.x;  // 256
    float s0 = 0.f, s1 = 0.f;
#pragma unroll 4
    for (int j = 0; j < CH2; j++) {
        const float* p = &g_part[((size_t)c * CH2 + j) * D];
        s0 += p[t];
        s1 += p[t + 256];
    }
    float ss = s0 * s0 + s1 * s1;
    __shared__ float red[8];
#pragma unroll
    for (int o = 16; o; o >>= 1) ss += __shfl_xor_sync(0xffffffffu, ss, o);
    if ((t & 31) == 0) red[t >> 5] = ss;
    __syncthreads();
    float tot;
    {
        float v = (t < 8) ? red[t] : 0.f;
#pragma unroll
        for (int o = 4; o; o >>= 1) v += __shfl_xor_sync(0xffffffffu, v, o);
        __shared__ float sh_tot;
        if (t == 0) sh_tot = v;
        __syncthreads();
        tot = sh_tot;
    }
    float rn = 1.f / fmaxf(sqrtf(tot), 1e-12f);
    g_Wcn[c * D + t] = s0 * rn;
    g_Wcn[c * D + t + 256] = s1 * rn;
}

// ---- kernel 7: final GEMM out = feature @ w_norm --------------------------
__global__ void k_gemm2(const float* __restrict__ feat, float* __restrict__ out,
                        int B) {
    int tid = blockIdx.x * blockDim.x + threadIdx.x;
    int warp = tid >> 5;
    int lane = threadIdx.x & 31;
    if (warp >= B) return;
    const float* f = feat + (size_t)warp * D;
    float fv[16];
#pragma unroll
    for (int j = 0; j < 16; j++) fv[j] = f[lane + 32 * j];
    float myv = 0.f;
#pragma unroll 1
    for (int c = 0; c < C; c++) {
        const float* wc = &g_Wcn[c * D];
        float s = 0.f;
#pragma unroll
        for (int j = 0; j < 16; j++) s += fv[j] * wc[lane + 32 * j];
#pragma unroll
        for (int o = 16; o; o >>= 1) s += __shfl_xor_sync(0xffffffffu, s, o);
        if (lane == c) myv = s;
    }
    if (lane < C) out[(size_t)warp * C + lane] = myv;
}

// ---- launch ---------------------------------------------------------------
extern "C" void kernel_launch(void* const* d_in, const int* in_sizes, int n_in,
                              void* d_out, int out_size) {
    const float* feature  = (const float*)d_in[0];
    const float* clf_w    = (const float*)d_in[1];
    const float* clf_b    = (const float*)d_in[2];
    const float* supports = (const float*)d_in[3];
    const float* ent_bank = (const float*)d_in[4];
    const int*   labels   = (const int*)d_in[5];
    const int*   kptr     = (const int*)d_in[6];

    int Cc = in_sizes[2];          // 17
    int Dv = in_sizes[1] / Cc;     // 512
    int B  = in_sizes[0] / Dv;     // 4096
    int N  = in_sizes[4];          // 100000
    int R  = N + B;
    (void)n_in; (void)out_size; (void)Dv;

    float* out = (float*)d_out;

    int blk1 = (B * 32 + 255) / 256;
    k_logits<<<blk1, 256>>>(feature, clf_w, clf_b, ent_bank, labels, B, N);
    k_scanA<<<C, 256>>>(kptr);
    k_compact<<<256, 256>>>(R);
    k_sel<<<C, 256>>>();
    dim3 g5(CH2, C);
    k_sum<<<g5, 256>>>(supports, feature, N);
    k_finalW<<<C, 256>>>();
    k_gemm2<<<blk1, 256>>>(feature, out, B);
}

// round 4
// speedup vs baseline: 2.5467x; 1.0472x over previous
#include <cuda_runtime.h>
#include <math.h>
#include <stdint.h>

#define D 512
#define C 17
#define RMAX 131072
#define NBA 4096
#define CANDCAP 32768
#define SELCAP 4096
#define LCAP 4096
#define CH2 64

// ---------------- device scratch (static; zero-init at module load) -------
__device__ unsigned g_entbits[RMAX];
__device__ int      g_cls[RMAX];
__device__ unsigned g_histA[C * NBA];   // re-zeroed by k_sel each run
__device__ unsigned g_prefA[C];
__device__ int      g_kleft[C];
__device__ int      g_cnt[C];
__device__ int      g_candcnt[C];
__device__ int      g_cand[C][CANDCAP];
__device__ int      g_list[(size_t)C * LCAP];
__device__ float    g_part[(size_t)C * CH2 * D];
__device__ float    g_Wcn[C * D];

// ---- kernel 1: bank keys + new-row logits/entropy/argmax, hist pass A ----
__global__ void k_logits(const float* __restrict__ feat,
                         const float* __restrict__ w,
                         const float* __restrict__ bias,
                         const float* __restrict__ entbank,
                         const int*   __restrict__ labels,
                         int B, int N) {
    int tid = blockIdx.x * blockDim.x + threadIdx.x;
    int nth = gridDim.x * blockDim.x;
    for (int i = tid; i < N; i += nth) {
        unsigned bits = __float_as_uint(entbank[i]);  // entropies >= 0: monotone
        int c = labels[i];
        g_entbits[i] = bits;
        g_cls[i] = c;
        atomicAdd(&g_histA[c * NBA + (bits >> 20)], 1u);
    }

    int warp = tid >> 5;
    int lane = threadIdx.x & 31;
    if (warp >= B) return;

    const float* f = feat + (size_t)warp * D;
    float fv[16];
#pragma unroll
    for (int j = 0; j < 16; j++) fv[j] = f[lane + 32 * j];

    float pc = -INFINITY;
#pragma unroll 1
    for (int c = 0; c < C; c++) {
        const float* wc = w + (size_t)c * D;
        float s = 0.f;
#pragma unroll
        for (int j = 0; j < 16; j++) s += fv[j] * wc[lane + 32 * j];
#pragma unroll
        for (int o = 16; o; o >>= 1) s += __shfl_xor_sync(0xffffffffu, s, o);
        if (lane == c) pc = s + bias[c];
    }
    float m = pc;
#pragma unroll
    for (int o = 16; o; o >>= 1) m = fmaxf(m, __shfl_xor_sync(0xffffffffu, m, o));

    float ex = (lane < C) ? expf(pc - m) : 0.f;
    float tt = (lane < C) ? ex * (pc - m) : 0.f;
    float S = ex, T = tt;
#pragma unroll
    for (int o = 16; o; o >>= 1) {
        S += __shfl_xor_sync(0xffffffffu, S, o);
        T += __shfl_xor_sync(0xffffffffu, T, o);
    }
    float ent = logf(S) - T / S;
    unsigned bal = __ballot_sync(0xffffffffu, (lane < C) && (pc == m));
    int amax = __ffs(bal) - 1;
    if (lane == 0) {
        unsigned bits = __float_as_uint(ent);
        g_entbits[N + warp] = bits;
        g_cls[N + warp] = amax;
        atomicAdd(&g_histA[amax * NBA + (bits >> 20)], 1u);
    }
}

// ---- kernel 2: scan pass A (parallel prefix) -> 12-bit bin per class -----
__global__ void k_scanA(const int* __restrict__ kptr) {
    int c = blockIdx.x;
    int t = threadIdx.x;  // 256
    const unsigned* h = &g_histA[c * NBA];
    __shared__ unsigned chunk[256];
    __shared__ unsigned incl[256];
    unsigned s = 0;
#pragma unroll
    for (int j = 0; j < 16; j++) s += h[t * 16 + j];
    chunk[t] = s;
    incl[t] = s;
    __syncthreads();
    // Hillis-Steele inclusive scan
#pragma unroll
    for (int off = 1; off < 256; off <<= 1) {
        unsigned v = (t >= off) ? incl[t - off] : 0u;
        __syncthreads();
        incl[t] += v;
        __syncthreads();
    }
    int tot = (int)incl[255];
    int Kf = kptr[0];
    int k = tot < Kf ? tot : Kf;
    if (t == 0) {
        g_cnt[c] = 0;
        g_candcnt[c] = 0;
        if (k <= 0) { g_prefA[c] = 0u; g_kleft[c] = 0; }
    }
    if (k <= 0) return;
    int excl = (int)incl[t] - (int)chunk[t];
    if ((int)incl[t] >= k && excl < k) {
        int run = excl;
        for (int q = 0; q < 16; q++) {
            unsigned v = h[t * 16 + q];
            if (run + (int)v >= k) {
                g_prefA[c] = (unsigned)(t * 16 + q);
                g_kleft[c] = k - run;
                break;
            }
            run += (int)v;
        }
    }
}

// ---- kernel 3: compact strict-below rows + gather pass-A-bin candidates --
__global__ void k_compact(int R) {
    __shared__ unsigned s_pref[C];
    if (threadIdx.x < C) s_pref[threadIdx.x] = g_prefA[threadIdx.x];
    __syncthreads();
    int tid = blockIdx.x * blockDim.x + threadIdx.x;
    int nth = gridDim.x * blockDim.x;
    for (int i = tid; i < R; i += nth) {
        int c = g_cls[i];
        unsigned b = g_entbits[i] >> 20;
        unsigned pa = s_pref[c];
        bool below = (b < pa);
        bool equal = (b == pa);
        // warp-aggregated push for "below"
        unsigned act = __ballot_sync(0xffffffffu, below);
        if (below) {
            unsigned peers = __match_any_sync(act, c);
            int leader = __ffs(peers) - 1;
            int rank = __popc(peers & ((1u << (threadIdx.x & 31)) - 1u));
            int base = 0;
            if ((threadIdx.x & 31) == leader)
                base = atomicAdd(&g_cnt[c], __popc(peers));
            base = __shfl_sync(peers, base, leader);
            g_list[(size_t)c * LCAP + base + rank] = i;
        }
        unsigned act2 = __ballot_sync(0xffffffffu, equal);
        if (equal) {
            unsigned peers = __match_any_sync(act2, c);
            int leader = __ffs(peers) - 1;
            int rank = __popc(peers & ((1u << (threadIdx.x & 31)) - 1u));
            int base = 0;
            if ((threadIdx.x & 31) == leader)
                base = atomicAdd(&g_candcnt[c], __popc(peers));
            base = __shfl_sync(peers, base, leader);
            int p = base + rank;
            if (p < CANDCAP) g_cand[c][p] = i;
        }
    }
}

// ---- kernel 4: exact select among candidates (parallel counting) ---------
__global__ void k_sel() {
    int c = blockIdx.x;
    int t = threadIdx.x;  // 256
    int k = g_kleft[c];
    int m = g_candcnt[c]; if (m > CANDCAP) m = CANDCAP;
    const int* lst = g_cand[c];

    __shared__ unsigned skey[SELCAP];
    __shared__ int      sidx[SELCAP];

    if (k > 0 && m > 0) {
        bool use_sh = (m <= SELCAP);
        if (use_sh) {
            for (int j = t; j < m; j += 256) {
                int idx = lst[j];
                skey[j] = g_entbits[idx];
                sidx[j] = idx;
            }
            __syncthreads();
            for (int j = t; j < m; j += 256) {
                unsigned key = skey[j];
                int idx = sidx[j];
                int rank = 0;
                for (int q = 0; q < m; q++) {
                    unsigned kq = skey[q];
                    rank += (kq < key) || (kq == key && sidx[q] < idx);
                }
                if (rank < k) {
                    int p = atomicAdd(&g_cnt[c], 1);
                    g_list[(size_t)c * LCAP + p] = idx;
                }
            }
        } else {
            // fallback: same counting, keys from global (L2-broadcast)
            for (int j = t; j < m; j += 256) {
                int idx = lst[j];
                unsigned key = g_entbits[idx];
                int rank = 0;
                for (int q = 0; q < m; q++) {
                    int iq = lst[q];
                    unsigned kq = g_entbits[iq];
                    rank += (kq < key) || (kq == key && iq < idx);
                }
                if (rank < k) {
                    int p = atomicAdd(&g_cnt[c], 1);
                    g_list[(size_t)c * LCAP + p] = idx;
                }
            }
        }
    }
    // restore zero-histogram invariant for the next run
    for (int i = t; i < NBA; i += 256) g_histA[c * NBA + i] = 0u;
}

// ---- kernel 5: normalized per-class support sums (register accumulate) ---
__global__ void k_sum(const float* __restrict__ supports,
                      const float* __restrict__ feat, int N) {
    int c = blockIdx.y;
    int blk = blockIdx.x;
    int cnt = g_cnt[c]; if (cnt > LCAP) cnt = LCAP;
    int w = threadIdx.x >> 5, lane = threadIdx.x & 31;
    int wg = blk * 8 + w;
    const int* lst = &g_list[(size_t)c * LCAP];

    float acc[16];
#pragma unroll
    for (int j = 0; j < 16; j++) acc[j] = 0.f;

    for (int idx = wg; idx < cnt; idx += CH2 * 8) {
        int r = lst[idx];
        const float4* p = (const float4*)((r < N) ? supports + (size_t)r * D
                                                  : feat + (size_t)(r - N) * D);
        float4 v[4];
        float ss = 0.f;
#pragma unroll
        for (int j = 0; j < 4; j++) {
            v[j] = p[lane + 32 * j];
            ss += v[j].x * v[j].x + v[j].y * v[j].y + v[j].z * v[j].z + v[j].w * v[j].w;
        }
#pragma unroll
        for (int o = 16; o; o >>= 1) ss += __shfl_xor_sync(0xffffffffu, ss, o);
        float rn = 1.f / fmaxf(sqrtf(ss), 1e-12f);
#pragma unroll
        for (int j = 0; j < 4; j++) {
            acc[4 * j + 0] += v[j].x * rn;
            acc[4 * j + 1] += v[j].y * rn;
            acc[4 * j + 2] += v[j].z * rn;
            acc[4 * j + 3] += v[j].w * rn;
        }
    }

    __shared__ float sacc[D];
    for (int d = threadIdx.x; d < D; d += blockDim.x) sacc[d] = 0.f;
    __syncthreads();
#pragma unroll
    for (int j = 0; j < 4; j++) {
        int d = 4 * (lane + 32 * j);
        atomicAdd(&sacc[d + 0], acc[4 * j + 0]);
        atomicAdd(&sacc[d + 1], acc[4 * j + 1]);
        atomicAdd(&sacc[d + 2], acc[4 * j + 2]);
        atomicAdd(&sacc[d + 3], acc[4 * j + 3]);
    }
    __syncthreads();
    float* dst = &g_part[((size_t)c * CH2 + blk) * D];
    for (int d = threadIdx.x; d < D; d += blockDim.x) dst[d] = sacc[d];
}

// ---- kernel 6: reduce partials + column-normalize ------------------------
__global__ void k_finalW() {
    int c = blockIdx.x;
    int t = threadIdx.x;  // 256
    float s0 = 0.f, s1 = 0.f;
#pragma unroll 4
    for (int j = 0; j < CH2; j++) {
        const float* p = &g_part[((size_t)c * CH2 + j) * D];
        s0 += p[t];
        s1 += p[t + 256];
    }
    float ss = s0 * s0 + s1 * s1;
    __shared__ float red[8];
#pragma unroll
    for (int o = 16; o; o >>= 1) ss += __shfl_xor_sync(0xffffffffu, ss, o);
    if ((t & 31) == 0) red[t >> 5] = ss;
    __syncthreads();
    float tot;
    {
        float v = (t < 8) ? red[t] : 0.f;
#pragma unroll
        for (int o = 4; o; o >>= 1) v += __shfl_xor_sync(0xffffffffu, v, o);
        __shared__ float sh_tot;
        if (t == 0) sh_tot = v;
        __syncthreads();
        tot = sh_tot;
    }
    float rn = 1.f / fmaxf(sqrtf(tot), 1e-12f);
    g_Wcn[c * D + t] = s0 * rn;
    g_Wcn[c * D + t + 256] = s1 * rn;
}

// ---- kernel 7: final GEMM out = feature @ w_norm --------------------------
__global__ void k_gemm2(const float* __restrict__ feat, float* __restrict__ out,
                        int B) {
    int tid = blockIdx.x * blockDim.x + threadIdx.x;
    int warp = tid >> 5;
    int lane = threadIdx.x & 31;
    if (warp >= B) return;
    const float* f = feat + (size_t)warp * D;
    float fv[16];
#pragma unroll
    for (int j = 0; j < 16; j++) fv[j] = f[lane + 32 * j];
    float myv = 0.f;
#pragma unroll 1
    for (int c = 0; c < C; c++) {
        const float* wc = &g_Wcn[c * D];
        float s = 0.f;
#pragma unroll
        for (int j = 0; j < 16; j++) s += fv[j] * wc[lane + 32 * j];
#pragma unroll
        for (int o = 16; o; o >>= 1) s += __shfl_xor_sync(0xffffffffu, s, o);
        if (lane == c) myv = s;
    }
    if (lane < C) out[(size_t)warp * C + lane] = myv;
}

// ---- launch ---------------------------------------------------------------
extern "C" void kernel_launch(void* const* d_in, const int* in_sizes, int n_in,
                              void* d_out, int out_size) {
    const float* feature  = (const float*)d_in[0];
    const float* clf_w    = (const float*)d_in[1];
    const float* clf_b    = (const float*)d_in[2];
    const float* supports = (const float*)d_in[3];
    const float* ent_bank = (const float*)d_in[4];
    const int*   labels   = (const int*)d_in[5];
    const int*   kptr     = (const int*)d_in[6];

    int Cc = in_sizes[2];          // 17
    int Dv = in_sizes[1] / Cc;     // 512
    int B  = in_sizes[0] / Dv;     // 4096
    int N  = in_sizes[4];          // 100000
    int R  = N + B;
    (void)n_in; (void)out_size; (void)Dv;

    float* out = (float*)d_out;

    int blk1 = (B * 32 + 255) / 256;
    k_logits<<<blk1, 256>>>(feature, clf_w, clf_b, ent_bank, labels, B, N);
    k_scanA<<<C, 256>>>(kptr);
    k_compact<<<256, 256>>>(R);
    k_sel<<<C, 256>>>();
    dim3 g5(CH2, C);
    k_sum<<<g5, 256>>>(supports, feature, N);
    k_finalW<<<C, 256>>>();
    k_gemm2<<<blk1, 256>>>(feature, out, B);
}